// round 12
// baseline (speedup 1.0000x reference)
#include <cuda_runtime.h>
#include <cuda_fp16.h>
#include <cstdint>

// ---------------- problem constants (fixed by the dataset) ----------------
#define NN    50000
#define EE    640000
#define HH    4
#define CC    32
#define RR    8
#define HC    128           // H*C
#define RNSEG (RR*NN)       // 400000 segments
#define QKVP  96            // q|k|v packed columns
#define NODEP 416           // Wj|Wi|Wsn|Wself packed columns
#define NB1   391           // ceil(RNSEG/1024) scan blocks

// ---------------- device scratch (static: no runtime allocation) ----------
__device__ __align__(16) float   g_hj  [NN*HC];            // 25.6 MB
__device__ __align__(16) float   g_hi  [NN*HC];            // 25.6 MB
__device__ __align__(16) float   g_sn  [NN*HC];            // 25.6 MB
__device__ __align__(16) float   g_self[NN*CC];            //  6.4 MB
__device__ __align__(16) __half  g_xh[NN*HC];              // x hi split
__device__ __align__(16) __half  g_xl[NN*HC];              // x lo split
__device__ __align__(16) __half  g_zh[(size_t)RR*NN*HC];   // z hi 51.2 MB
__device__ __align__(16) __half  g_zl[(size_t)RR*NN*HC];   // z lo 51.2 MB
__device__ __align__(16) float   g_qkvb[(size_t)RR*NN*QKVP]; // 153.6 MB
__device__ __align__(16) __half  g_wnh[NODEP*HC];          // node W^T hi [p][k]
__device__ __align__(16) __half  g_wnl[NODEP*HC];          // node W^T lo
__device__ __align__(16) __half  g_wqh[RR*QKVP*HC];        // qkv  W^T hi [r][j][k]
__device__ __align__(16) __half  g_wql[RR*QKVP*HC];        // qkv  W^T lo
__device__ int   g_cnt   [RNSEG];
__device__ int   g_start [RNSEG];
__device__ int   g_cursor[RNSEG];
__device__ int   g_ssrc  [EE];
__device__ int   g_bsum  [512];
__device__ int   g_ei64;
__device__ int   g_et64;

// ---------------- helpers --------------------------------------------------
__device__ __forceinline__ uint32_t smem_u32(const void* p) {
    uint32_t a;
    asm("{ .reg .u64 t; cvta.to.shared.u64 t, %1; cvt.u32.u64 %0, t; }"
        : "=r"(a) : "l"(p));
    return a;
}

__device__ __forceinline__ void ldm_x4(uint32_t* r, uint32_t a) {
    asm volatile("ldmatrix.sync.aligned.m8n8.x4.shared.b16 {%0,%1,%2,%3}, [%4];"
                 : "=r"(r[0]), "=r"(r[1]), "=r"(r[2]), "=r"(r[3]) : "r"(a));
}

__device__ __forceinline__ void mma16816(float* c, const uint32_t* a, const uint32_t* b) {
    asm volatile(
        "mma.sync.aligned.m16n8k16.row.col.f32.f16.f16.f32 "
        "{%0,%1,%2,%3}, {%4,%5,%6,%7}, {%8,%9}, {%0,%1,%2,%3};"
        : "+f"(c[0]), "+f"(c[1]), "+f"(c[2]), "+f"(c[3])
        : "r"(a[0]), "r"(a[1]), "r"(a[2]), "r"(a[3]), "r"(b[0]), "r"(b[1]));
}

__device__ __forceinline__ void cpa16(uint32_t dst, const void* src, int sz) {
    asm volatile("cp.async.cg.shared.global [%0], [%1], 16, %2;"
                 :: "r"(dst), "l"(src), "r"(sz) : "memory");
}

// ---------------- dtype sniffing -------------------------------------------
__global__ void k_detect(const int* __restrict__ ei_raw,
                         const int* __restrict__ et_raw)
{
    int a = 1, b = 1;
    for (int i = 0; i < 128; i++) {
        if (ei_raw[2 * i + 1] != 0) a = 0;
        if (et_raw[2 * i + 1] != 0) b = 0;
    }
    g_ei64 = a;
    g_et64 = b;
}

__device__ __forceinline__ int load_idx(const int* __restrict__ p, int i, int is64)
{
    return is64 ? p[2 * i] : p[i];
}

// ---------------- fp16 hi/lo split + weight packing ------------------------
__global__ void k_split_x(const float* __restrict__ x)
{
    int i = blockIdx.x * blockDim.x + threadIdx.x;
    if (i >= NN * HC) return;
    float v = x[i];
    __half h = __float2half(v);
    g_xh[i] = h;
    g_xl[i] = __float2half(v - __half2float(h));
}

__global__ void k_packw(const float* __restrict__ Wj, const float* __restrict__ Wi,
                        const float* __restrict__ Wsn, const float* __restrict__ Wself)
{
    int i = blockIdx.x * blockDim.x + threadIdx.x;   // p*128 + k
    if (i >= NODEP * HC) return;
    int k = i & 127, p = i >> 7;
    float v;
    if      (p < 128) v = Wj  [k * 128 + p];
    else if (p < 256) v = Wi  [k * 128 + (p - 128)];
    else if (p < 384) v = Wsn [k * 128 + (p - 256)];
    else              v = Wself[k * 32 + (p - 384)];
    __half h = __float2half(v);
    g_wnh[i] = h;
    g_wnl[i] = __float2half(v - __half2float(h));
}

__global__ void k_packq(const float* __restrict__ Wq, const float* __restrict__ Wk,
                        const float* __restrict__ Wv)
{
    int i = blockIdx.x * blockDim.x + threadIdx.x;   // r*96*128 + j*128 + k
    if (i >= RR * QKVP * HC) return;
    int k = i & 127;
    int j = (i >> 7) % QKVP;
    int r = i / (QKVP * HC);
    float v;
    if      (j < 32) v = Wq[((r * 128) + k) * 32 + j];
    else if (j < 64) v = Wk[((r * 128) + k) * 32 + (j - 32)];
    else             v = Wv[((r * 128) + k) * 32 + (j - 64)];
    __half h = __float2half(v);
    g_wqh[i] = h;
    g_wql[i] = __float2half(v - __half2float(h));
}

// ---------------- fp16-split HMMA GEMM (mma.sync, sm_80-level PTX) ---------
// C[M,P] = (Ah+Al)[M,128] @ (Bh+Bl)^T, B stored [P][128] K-major.
// 3 passes: Ah*Bh + Al*Bh + Ah*Bl, fp32 accum (dropped Al*Bl ~ 2^-24).
// CTA 256 thr (8 warps stacked in M), tile 128 x NT, warp tile 16 x NT.
// smem <= ~105 KB and regs <= 128 so TWO CTAs co-reside per SM (the GEMM is
// latency-bound; cross-CTA overlap hides stage + ldm->mma latency).
#define ROWB   272
#define ASZ    (128 * ROWB)                 // per split: 34816

template<int NT, int MODE>
__global__ __launch_bounds__(256, 2)
void tgemm(const __half* __restrict__ Ah, const __half* __restrict__ Al,
           const __half* __restrict__ Bh, const __half* __restrict__ Bl,
           float* __restrict__ C, int M, int Prows,
           long long sA, long long sB, long long sC)
{
    extern __shared__ __align__(16) char sm[];
    const int tid = threadIdx.x;
    const int l   = tid & 31, w = tid >> 5;
    const int m0  = blockIdx.y * 128;
    const int n0  = blockIdx.x * NT;
    Ah += (long long)blockIdx.z * sA;  Al += (long long)blockIdx.z * sA;
    Bh += (long long)blockIdx.z * sB;  Bl += (long long)blockIdx.z * sB;
    C  += (long long)blockIdx.z * sC;

    char* smA0 = sm;
    char* smA1 = sm + ASZ;
    char* smB0 = sm + 2 * ASZ;
    char* smB1 = sm + 2 * ASZ + NT * ROWB;
    const uint32_t sbA0 = smem_u32(smA0), sbA1 = smem_u32(smA1);
    const uint32_t sbB0 = smem_u32(smB0), sbB1 = smem_u32(smB1);

    // ---- async stage A hi/lo (128 rows x 128 fp16) and B hi/lo (NT rows) ----
    for (int i = tid; i < 2048; i += 256) {
        int row = i >> 4, c8 = i & 15;
        int gm = m0 + row;
        int ok = (gm < M);
        size_t off = (size_t)(ok ? gm : 0) * 128 + c8 * 8;
        int sz = ok ? 16 : 0;
        cpa16(sbA0 + row * ROWB + c8 * 16, Ah + off, sz);
        cpa16(sbA1 + row * ROWB + c8 * 16, Al + off, sz);
    }
    for (int i = tid; i < NT * 16; i += 256) {
        int row = i >> 4, c8 = i & 15;
        int gp = n0 + row;
        int ok = (gp < Prows);
        size_t off = (size_t)(ok ? gp : 0) * 128 + c8 * 8;
        int sz = ok ? 16 : 0;
        cpa16(sbB0 + row * ROWB + c8 * 16, Bh + off, sz);
        cpa16(sbB1 + row * ROWB + c8 * 16, Bl + off, sz);
    }
    asm volatile("cp.async.commit_group;" ::: "memory");
    asm volatile("cp.async.wait_group 0;" ::: "memory");
    __syncthreads();

    // ---- per-lane ldmatrix base addresses ----
    uint32_t aA0 = sbA0 + (w * 16 + (l & 15)) * ROWB + ((l >> 4) << 4);
    uint32_t aA1 = sbA1 + (w * 16 + (l & 15)) * ROWB + ((l >> 4) << 4);
    uint32_t aB0[NT / 16], aB1[NT / 16];
#pragma unroll
    for (int g = 0; g < NT / 16; g++) {
        uint32_t roff = (g * 16 + ((l >> 4) << 3) + (l & 7)) * ROWB + (((l >> 3) & 1) << 4);
        aB0[g] = sbB0 + roff;
        aB1[g] = sbB1 + roff;
    }

    float acc[NT / 8][4];
#pragma unroll
    for (int j = 0; j < NT / 8; j++)
#pragma unroll
        for (int q = 0; q < 4; q++) acc[j][q] = 0.f;

#pragma unroll
    for (int c = 0; c < 8; c++) {
        uint32_t af0[4], af1[4], bh[NT / 16][4], bl[NT / 16][4];
        ldm_x4(af0, aA0 + (c << 5));
        ldm_x4(af1, aA1 + (c << 5));
#pragma unroll
        for (int g = 0; g < NT / 16; g++) {
            ldm_x4(bh[g], aB0[g] + (c << 5));
            ldm_x4(bl[g], aB1[g] + (c << 5));
        }
#pragma unroll
        for (int j = 0; j < NT / 8; j++) {
            const uint32_t* bbh = &bh[j >> 1][2 * (j & 1)];
            const uint32_t* bbl = &bl[j >> 1][2 * (j & 1)];
            mma16816(acc[j], af0, bbh);   // Ah*Bh
            mma16816(acc[j], af1, bbh);   // Al*Bh
            mma16816(acc[j], af0, bbl);   // Ah*Bl
        }
    }

    // ---- epilogue: c-frag map (g=l>>2, t=l&3) ----
    const int gq = l >> 2, tq = l & 3;
#pragma unroll
    for (int j = 0; j < NT / 8; j++) {
        int col = n0 + j * 8 + 2 * tq;
#pragma unroll
        for (int half = 0; half < 2; half++) {
            int rr = m0 + w * 16 + gq + half * 8;
            if (rr >= M) continue;
            float2 v = make_float2(acc[j][2 * half], acc[j][2 * half + 1]);
            if (MODE == 0) {
                if (col < 128)
                    *(float2*)(g_hj + (size_t)rr * 128 + col) = v;
                else if (col < 256)
                    *(float2*)(g_hi + (size_t)rr * 128 + (col - 128)) = v;
                else if (col < 384)
                    *(float2*)(g_sn + (size_t)rr * 128 + (col - 256)) = v;
                else if (col < 416)
                    *(float2*)(g_self + (size_t)rr * 32 + (col - 384)) = v;
            } else {
                if (col < Prows)
                    *(float2*)(C + (size_t)rr * Prows + col) = v;
            }
        }
    }
}

// ---------------- counting sort of edges by segment ------------------------
__global__ void k_zero()
{
    int i = blockIdx.x * blockDim.x + threadIdx.x;
    if (i < RNSEG) { g_cnt[i] = 0; g_cursor[i] = 0; }
}

__global__ void k_hist(const int* __restrict__ ei, const int* __restrict__ et)
{
    int e = blockIdx.x * blockDim.x + threadIdx.x;
    if (e >= EE) return;
    int i64 = g_ei64, t64 = g_et64;
    int dst = load_idx(ei, EE + e, i64);
    int r   = load_idx(et, e, t64);
    atomicAdd(&g_cnt[r * NN + dst], 1);
}

__global__ void k_scan1()
{
    __shared__ int sh[256];
    int t = threadIdx.x;
    int base = blockIdx.x * 1024 + t * 4;
    int v0 = 0, v1 = 0, v2 = 0, v3 = 0;
    if (base + 0 < RNSEG) v0 = g_cnt[base + 0];
    if (base + 1 < RNSEG) v1 = g_cnt[base + 1];
    if (base + 2 < RNSEG) v2 = g_cnt[base + 2];
    if (base + 3 < RNSEG) v3 = g_cnt[base + 3];
    int local = v0 + v1 + v2 + v3;
    sh[t] = local;
    __syncthreads();
    for (int off = 1; off < 256; off <<= 1) {
        int x = 0;
        if (t >= off) x = sh[t - off];
        __syncthreads();
        if (t >= off) sh[t] += x;
        __syncthreads();
    }
    int run = sh[t] - local;
    if (base + 0 < RNSEG) g_start[base + 0] = run;  run += v0;
    if (base + 1 < RNSEG) g_start[base + 1] = run;  run += v1;
    if (base + 2 < RNSEG) g_start[base + 2] = run;  run += v2;
    if (base + 3 < RNSEG) g_start[base + 3] = run;
    if (t == 255) g_bsum[blockIdx.x] = sh[255];
}

__global__ void k_scan2(int nb)
{
    __shared__ int sh[512];
    int t = threadIdx.x;
    int val = (t < nb) ? g_bsum[t] : 0;
    sh[t] = val;
    __syncthreads();
    for (int off = 1; off < 512; off <<= 1) {
        int x = 0;
        if (t >= off) x = sh[t - off];
        __syncthreads();
        if (t >= off) sh[t] += x;
        __syncthreads();
    }
    if (t < nb) g_bsum[t] = sh[t] - val;
}

__global__ void k_scan3()
{
    int i = blockIdx.x * blockDim.x + threadIdx.x;
    if (i < RNSEG) g_start[i] += g_bsum[i >> 10];
}

__global__ void k_scatter(const int* __restrict__ ei, const int* __restrict__ et)
{
    int e = blockIdx.x * blockDim.x + threadIdx.x;
    if (e >= EE) return;
    int i64 = g_ei64, t64 = g_et64;
    int src = load_idx(ei, e, i64);
    int dst = load_idx(ei, EE + e, i64);
    int r   = load_idx(et, e, t64);
    int seg = r * NN + dst;
    int pos = g_start[seg] + atomicAdd(&g_cursor[seg], 1);
    g_ssrc[pos] = src;
}

// ---------------- per-segment softmax-weighted aggregation -----------------
// One warp per segment (r,n). SINGLE gather pass (online, no max subtraction):
// acc = sum e_j * xj, denom = sum e_j; z = sn + acc/(denom+eps).
// Identical math to the two-pass version; half the L2 gather traffic.
__global__ void k_agg(const float* __restrict__ natt)
{
    int w    = (blockIdx.x * blockDim.x + threadIdx.x) >> 5;
    int lane = threadIdx.x & 31;
    if (w >= RNSEG) return;
    int r  = w / NN;
    int n  = w - r * NN;
    int d0 = lane * 4;

    float4 sn4 = *(const float4*)(g_sn + (size_t)n * HC + d0);
    float4 acc = make_float4(0.f, 0.f, 0.f, 0.f);
    float denom = 0.f;
    int cnt = g_cnt[w];

    if (cnt > 0) {
        int st = g_start[w];
        float4 xi = *(const float4*)(g_hi + (size_t)n * HC + d0);
        int h  = lane >> 3;
        int cb = (lane & 7) * 4;
        const float* ab = natt + (r * HH + h) * (2 * CC);
        float4 ai = *(const float4*)(ab + cb);
        float4 aj = *(const float4*)(ab + CC + cb);

        float pi = ai.x * xi.x + ai.y * xi.y + ai.z * xi.z + ai.w * xi.w;
        pi += __shfl_xor_sync(0xffffffffu, pi, 1);
        pi += __shfl_xor_sync(0xffffffffu, pi, 2);
        pi += __shfl_xor_sync(0xffffffffu, pi, 4);

        for (int j = 0; j < cnt; j++) {
            int src = g_ssrc[st + j];
            float4 xj = *(const float4*)(g_hj + (size_t)src * HC + d0);
            float pj = aj.x * xj.x + aj.y * xj.y + aj.z * xj.z + aj.w * xj.w;
            pj += __shfl_xor_sync(0xffffffffu, pj, 1);
            pj += __shfl_xor_sync(0xffffffffu, pj, 2);
            pj += __shfl_xor_sync(0xffffffffu, pj, 4);
            float al = pi + pj;
            al = (al > 0.f) ? al : 0.2f * al;        // leaky relu
            float e = __expf(al);
            denom += e;
            acc.x += e * xj.x; acc.y += e * xj.y;
            acc.z += e * xj.z; acc.w += e * xj.w;
        }
        float inv = 1.f / (denom + 1e-16f);
        acc.x *= inv; acc.y *= inv; acc.z *= inv; acc.w *= inv;
    }
    float zr[4] = { sn4.x + acc.x, sn4.y + acc.y, sn4.z + acc.z, sn4.w + acc.w };
    __half hh[4], ll[4];
#pragma unroll
    for (int t = 0; t < 4; t++) {
        hh[t] = __float2half(zr[t]);
        ll[t] = __float2half(zr[t] - __half2float(hh[t]));
    }
    *(uint2*)(g_zh + (size_t)w * HC + d0) = *(uint2*)hh;
    *(uint2*)(g_zl + (size_t)w * HC + d0) = *(uint2*)ll;
}

// ---------------- relation-level attention + output ------------------------
__global__ void k_final(const float* __restrict__ wrel, float* __restrict__ out)
{
    int n    = (blockIdx.x * blockDim.x + threadIdx.x) >> 5;
    int lane = threadIdx.x & 31;
    if (n >= NN) return;

    float q[RR], kk[RR], vv[RR];
#pragma unroll
    for (int r = 0; r < RR; r++) {
        const float* p = g_qkvb + ((size_t)r * NN + n) * QKVP;
        q[r]  = p[lane];
        kk[r] = p[32 + lane];
        vv[r] = p[64 + lane];
    }
    float selfc = g_self[(size_t)n * CC + lane];
    float o = 0.f;

#pragma unroll
    for (int r = 0; r < RR; r++) {
        float t[RR];
#pragma unroll
        for (int s = 0; s < RR; s++) t[s] = q[r] * kk[s];
#pragma unroll
        for (int off = 16; off > 0; off >>= 1)
#pragma unroll
            for (int s = 0; s < RR; s++)
                t[s] += __shfl_xor_sync(0xffffffffu, t[s], off);
        float m = t[0];
#pragma unroll
        for (int s = 1; s < RR; s++) m = fmaxf(m, t[s]);
        float psum = 0.f, dacc = 0.f;
#pragma unroll
        for (int s = 0; s < RR; s++) {
            float e = __expf(t[s] - m);
            psum += e;
            dacc += e * vv[s];
        }
        float delta = dacc / psum;
        float sd = delta;
#pragma unroll
        for (int off = 16; off > 0; off >>= 1)
            sd += __shfl_xor_sync(0xffffffffu, sd, off);
        float mask = (sd != 0.f) ? 1.f : 0.f;
        o += (delta + selfc * mask) * wrel[r];
    }
    out[n * CC + lane] = o;
}

// ---------------- host launcher --------------------------------------------
extern "C" void kernel_launch(void* const* d_in, const int* in_sizes, int n_in,
                              void* d_out, int out_size)
{
    (void)in_sizes; (void)n_in; (void)out_size;
    const float* x    = (const float*)d_in[0];
    const int*   ei   = (const int*)d_in[1];    // int32 OR int64 (sniffed)
    const int*   et   = (const int*)d_in[2];
    const float* Wj   = (const float*)d_in[3];
    const float* Wi   = (const float*)d_in[4];
    const float* natt = (const float*)d_in[5];
    const float* Wq   = (const float*)d_in[6];
    const float* Wk   = (const float*)d_in[7];
    const float* Wv   = (const float*)d_in[8];
    const float* Wself= (const float*)d_in[9];
    const float* Wsn  = (const float*)d_in[10];
    const float* Wrel = (const float*)d_in[11];
    float*       out  = (float*)d_out;

    const int SM_NODE = 2 * ASZ + 2 * 64 * ROWB;   // 104448 -> 2 CTAs/SM
    const int SM_QKV  = 2 * ASZ + 2 * 48 * ROWB;   //  95744 -> 2 CTAs/SM
    cudaFuncSetAttribute(tgemm<64, 0>, cudaFuncAttributeMaxDynamicSharedMemorySize, SM_NODE);
    cudaFuncSetAttribute(tgemm<48, 1>, cudaFuncAttributeMaxDynamicSharedMemorySize, SM_QKV);

    void *xh, *xl, *zh, *zl, *qkv, *wnh, *wnl, *wqh, *wql;
    cudaGetSymbolAddress(&xh,  g_xh);   cudaGetSymbolAddress(&xl,  g_xl);
    cudaGetSymbolAddress(&zh,  g_zh);   cudaGetSymbolAddress(&zl,  g_zl);
    cudaGetSymbolAddress(&qkv, g_qkvb);
    cudaGetSymbolAddress(&wnh, g_wnh);  cudaGetSymbolAddress(&wnl, g_wnl);
    cudaGetSymbolAddress(&wqh, g_wqh);  cudaGetSymbolAddress(&wql, g_wql);

    const int MBLK = (NN + 127) / 128;   // 391

    // dtype sniff + input conversions
    k_detect<<<1, 1>>>(ei, et);
    k_split_x<<<(NN * HC + 255) / 256, 256>>>(x);
    k_packw<<<(NODEP * HC + 255) / 256, 256>>>(Wj, Wi, Wsn, Wself);
    k_packq<<<(RR * QKVP * HC + 255) / 256, 256>>>(Wq, Wk, Wv);

    // counting sort of edges by segment
    k_zero<<<(RNSEG + 255) / 256, 256>>>();
    k_hist<<<(EE + 255) / 256, 256>>>(ei, et);
    k_scan1<<<NB1, 256>>>();
    k_scan2<<<1, 512>>>(NB1);
    k_scan3<<<(RNSEG + 255) / 256, 256>>>();
    k_scatter<<<(EE + 255) / 256, 256>>>(ei, et);

    // fused node projections: [hj|hi|sn|self] = x @ [Wj|Wi|Wsn|Wself]
    tgemm<64, 0><<<dim3(7, MBLK, 1), 256, SM_NODE>>>(
        (const __half*)xh, (const __half*)xl,
        (const __half*)wnh, (const __half*)wnl,
        nullptr, NN, NODEP, 0, 0, 0);

    // per-segment attention aggregation -> z (fp16 hi/lo), single pass
    k_agg<<<RNSEG / 8, 256>>>(natt);

    // batched qkv projection: q|k|v[r] = z[r] @ [Wq|Wk|Wv][r] (2 x 48-col tiles)
    tgemm<48, 1><<<dim3(2, MBLK, RR), 256, SM_QKV>>>(
        (const __half*)zh, (const __half*)zl,
        (const __half*)wqh, (const __half*)wql,
        (float*)qkv, NN, QKVP,
        (long long)NN * HC, (long long)QKVP * HC, (long long)NN * QKVP);

    // relation attention + output
    k_final<<<(NN + 7) / 8, 256>>>(Wrel, out);
}

// round 13
// speedup vs baseline: 1.0588x; 1.0588x over previous
#include <cuda_runtime.h>
#include <cuda_fp16.h>
#include <cstdint>

// ---------------- problem constants (fixed by the dataset) ----------------
#define NN    50000
#define EE    640000
#define HH    4
#define CC    32
#define RR    8
#define HC    128           // H*C
#define RNSEG (RR*NN)       // 400000 segments
#define QKVP  96            // q|k|v packed columns
#define NODEP 416           // Wj|Wi|Wsn|Wself packed columns
#define NB1   391           // ceil(RNSEG/1024) scan blocks

// ---------------- device scratch (static: no runtime allocation) ----------
__device__ __align__(16) float   g_hj  [NN*HC];            // 25.6 MB
__device__ __align__(16) float   g_hi  [NN*HC];            // 25.6 MB
__device__ __align__(16) float   g_sn  [NN*HC];            // 25.6 MB
__device__ __align__(16) float   g_self[NN*CC];            //  6.4 MB
__device__ __align__(16) __half  g_xh[NN*HC];              // x hi split
__device__ __align__(16) __half  g_xl[NN*HC];              // x lo split
__device__ __align__(16) __half  g_zh[(size_t)RR*NN*HC];   // z hi 51.2 MB
__device__ __align__(16) __half  g_zl[(size_t)RR*NN*HC];   // z lo 51.2 MB
__device__ __align__(16) float   g_qkvb[(size_t)RR*NN*QKVP]; // 153.6 MB
__device__ __align__(16) __half  g_wnh[NODEP*HC];          // node W^T hi [p][k]
__device__ __align__(16) __half  g_wnl[NODEP*HC];          // node W^T lo
__device__ __align__(16) __half  g_wqh[RR*QKVP*HC];        // qkv  W^T hi [r][j][k]
__device__ __align__(16) __half  g_wql[RR*QKVP*HC];        // qkv  W^T lo
__device__ int   g_cnt   [RNSEG];
__device__ int   g_start [RNSEG];
__device__ int   g_cursor[RNSEG];
__device__ int   g_ssrc  [EE];
__device__ int   g_bsum  [512];
__device__ int   g_ei64;
__device__ int   g_et64;

// ---------------- helpers --------------------------------------------------
__device__ __forceinline__ uint32_t smem_u32(const void* p) {
    uint32_t a;
    asm("{ .reg .u64 t; cvta.to.shared.u64 t, %1; cvt.u32.u64 %0, t; }"
        : "=r"(a) : "l"(p));
    return a;
}

__device__ __forceinline__ void ldm_x4(uint32_t* r, uint32_t a) {
    asm volatile("ldmatrix.sync.aligned.m8n8.x4.shared.b16 {%0,%1,%2,%3}, [%4];"
                 : "=r"(r[0]), "=r"(r[1]), "=r"(r[2]), "=r"(r[3]) : "r"(a));
}

__device__ __forceinline__ void mma16816(float* c, const uint32_t* a, const uint32_t* b) {
    asm volatile(
        "mma.sync.aligned.m16n8k16.row.col.f32.f16.f16.f32 "
        "{%0,%1,%2,%3}, {%4,%5,%6,%7}, {%8,%9}, {%0,%1,%2,%3};"
        : "+f"(c[0]), "+f"(c[1]), "+f"(c[2]), "+f"(c[3])
        : "r"(a[0]), "r"(a[1]), "r"(a[2]), "r"(a[3]), "r"(b[0]), "r"(b[1]));
}

__device__ __forceinline__ void cpa16(uint32_t dst, const void* src, int sz) {
    asm volatile("cp.async.cg.shared.global [%0], [%1], 16, %2;"
                 :: "r"(dst), "l"(src), "r"(sz) : "memory");
}

// ---------------- dtype sniffing -------------------------------------------
__global__ void k_detect(const int* __restrict__ ei_raw,
                         const int* __restrict__ et_raw)
{
    int a = 1, b = 1;
    for (int i = 0; i < 128; i++) {
        if (ei_raw[2 * i + 1] != 0) a = 0;
        if (et_raw[2 * i + 1] != 0) b = 0;
    }
    g_ei64 = a;
    g_et64 = b;
}

__device__ __forceinline__ int load_idx(const int* __restrict__ p, int i, int is64)
{
    return is64 ? p[2 * i] : p[i];
}

// ---------------- fused prep: x split + weight packing (one launch) --------
#define PREP_X   (NN*HC)                       // 6400000
#define PREP_W   (NODEP*HC)                    //   53248
#define PREP_Q   (RR*QKVP*HC)                  //   98304
#define PREP_TOT (PREP_X + PREP_W + PREP_Q)

__global__ void k_prep(const float* __restrict__ x,
                       const float* __restrict__ Wj, const float* __restrict__ Wi,
                       const float* __restrict__ Wsn, const float* __restrict__ Wself,
                       const float* __restrict__ Wq, const float* __restrict__ Wk,
                       const float* __restrict__ Wv)
{
    int i = blockIdx.x * blockDim.x + threadIdx.x;
    if (i < PREP_X) {                      // x -> fp16 hi/lo split
        float v = x[i];
        __half h = __float2half(v);
        g_xh[i] = h;
        g_xl[i] = __float2half(v - __half2float(h));
        return;
    }
    i -= PREP_X;
    if (i < PREP_W) {                      // node weights^T, hi/lo
        int k = i & 127, p = i >> 7;
        float v;
        if      (p < 128) v = Wj  [k * 128 + p];
        else if (p < 256) v = Wi  [k * 128 + (p - 128)];
        else if (p < 384) v = Wsn [k * 128 + (p - 256)];
        else              v = Wself[k * 32 + (p - 384)];
        __half h = __float2half(v);
        g_wnh[i] = h;
        g_wnl[i] = __float2half(v - __half2float(h));
        return;
    }
    i -= PREP_W;
    if (i < PREP_Q) {                      // qkv weights^T, hi/lo
        int k = i & 127;
        int j = (i >> 7) % QKVP;
        int r = i / (QKVP * HC);
        float v;
        if      (j < 32) v = Wq[((r * 128) + k) * 32 + j];
        else if (j < 64) v = Wk[((r * 128) + k) * 32 + (j - 32)];
        else             v = Wv[((r * 128) + k) * 32 + (j - 64)];
        __half h = __float2half(v);
        g_wqh[i] = h;
        g_wql[i] = __float2half(v - __half2float(h));
    }
}

// ---------------- fp16-split HMMA GEMM (mma.sync, sm_80-level PTX) ---------
// C[M,P] = (Ah+Al)[M,128] @ (Bh+Bl)^T, B stored [P][128] K-major.
// 3 passes: Ah*Bh + Al*Bh + Ah*Bl, fp32 accum (dropped Al*Bl ~ 2^-24).
// CTA 256 thr (8 warps stacked in M), tile 128 x NT, warp tile 16 x NT.
// smem and regs sized so TWO CTAs co-reside per SM (latency-bound mainloop).
#define ROWB   272
#define ASZ    (128 * ROWB)                 // per split: 34816

template<int NT, int MODE>
__global__ __launch_bounds__(256, 2)
void tgemm(const __half* __restrict__ Ah, const __half* __restrict__ Al,
           const __half* __restrict__ Bh, const __half* __restrict__ Bl,
           float* __restrict__ C, int M, int Prows,
           long long sA, long long sB, long long sC)
{
    extern __shared__ __align__(16) char sm[];
    const int tid = threadIdx.x;
    const int l   = tid & 31, w = tid >> 5;
    const int m0  = blockIdx.y * 128;
    const int n0  = blockIdx.x * NT;
    Ah += (long long)blockIdx.z * sA;  Al += (long long)blockIdx.z * sA;
    Bh += (long long)blockIdx.z * sB;  Bl += (long long)blockIdx.z * sB;
    C  += (long long)blockIdx.z * sC;

    char* smA0 = sm;
    char* smA1 = sm + ASZ;
    char* smB0 = sm + 2 * ASZ;
    char* smB1 = sm + 2 * ASZ + NT * ROWB;
    const uint32_t sbA0 = smem_u32(smA0), sbA1 = smem_u32(smA1);
    const uint32_t sbB0 = smem_u32(smB0), sbB1 = smem_u32(smB1);

    // ---- async stage A hi/lo (128 rows x 128 fp16) and B hi/lo (NT rows) ----
    for (int i = tid; i < 2048; i += 256) {
        int row = i >> 4, c8 = i & 15;
        int gm = m0 + row;
        int ok = (gm < M);
        size_t off = (size_t)(ok ? gm : 0) * 128 + c8 * 8;
        int sz = ok ? 16 : 0;
        cpa16(sbA0 + row * ROWB + c8 * 16, Ah + off, sz);
        cpa16(sbA1 + row * ROWB + c8 * 16, Al + off, sz);
    }
    for (int i = tid; i < NT * 16; i += 256) {
        int row = i >> 4, c8 = i & 15;
        int gp = n0 + row;
        int ok = (gp < Prows);
        size_t off = (size_t)(ok ? gp : 0) * 128 + c8 * 8;
        int sz = ok ? 16 : 0;
        cpa16(sbB0 + row * ROWB + c8 * 16, Bh + off, sz);
        cpa16(sbB1 + row * ROWB + c8 * 16, Bl + off, sz);
    }
    asm volatile("cp.async.commit_group;" ::: "memory");
    asm volatile("cp.async.wait_group 0;" ::: "memory");
    __syncthreads();

    // ---- per-lane ldmatrix base addresses ----
    uint32_t aA0 = sbA0 + (w * 16 + (l & 15)) * ROWB + ((l >> 4) << 4);
    uint32_t aA1 = sbA1 + (w * 16 + (l & 15)) * ROWB + ((l >> 4) << 4);
    uint32_t aB0[NT / 16], aB1[NT / 16];
#pragma unroll
    for (int g = 0; g < NT / 16; g++) {
        uint32_t roff = (g * 16 + ((l >> 4) << 3) + (l & 7)) * ROWB + (((l >> 3) & 1) << 4);
        aB0[g] = sbB0 + roff;
        aB1[g] = sbB1 + roff;
    }

    float acc[NT / 8][4];
#pragma unroll
    for (int j = 0; j < NT / 8; j++)
#pragma unroll
        for (int q = 0; q < 4; q++) acc[j][q] = 0.f;

#pragma unroll
    for (int c = 0; c < 8; c++) {
        uint32_t af0[4], af1[4], bh[NT / 16][4], bl[NT / 16][4];
        ldm_x4(af0, aA0 + (c << 5));
        ldm_x4(af1, aA1 + (c << 5));
#pragma unroll
        for (int g = 0; g < NT / 16; g++) {
            ldm_x4(bh[g], aB0[g] + (c << 5));
            ldm_x4(bl[g], aB1[g] + (c << 5));
        }
#pragma unroll
        for (int j = 0; j < NT / 8; j++) {
            const uint32_t* bbh = &bh[j >> 1][2 * (j & 1)];
            const uint32_t* bbl = &bl[j >> 1][2 * (j & 1)];
            mma16816(acc[j], af0, bbh);   // Ah*Bh
            mma16816(acc[j], af1, bbh);   // Al*Bh
            mma16816(acc[j], af0, bbl);   // Ah*Bl
        }
    }

    // ---- epilogue: c-frag map (g=l>>2, t=l&3) ----
    const int gq = l >> 2, tq = l & 3;
#pragma unroll
    for (int j = 0; j < NT / 8; j++) {
        int col = n0 + j * 8 + 2 * tq;
#pragma unroll
        for (int half = 0; half < 2; half++) {
            int rr = m0 + w * 16 + gq + half * 8;
            if (rr >= M) continue;
            float2 v = make_float2(acc[j][2 * half], acc[j][2 * half + 1]);
            if (MODE == 0) {
                if (col < 128)
                    *(float2*)(g_hj + (size_t)rr * 128 + col) = v;
                else if (col < 256)
                    *(float2*)(g_hi + (size_t)rr * 128 + (col - 128)) = v;
                else if (col < 384)
                    *(float2*)(g_sn + (size_t)rr * 128 + (col - 256)) = v;
                else if (col < 416)
                    *(float2*)(g_self + (size_t)rr * 32 + (col - 384)) = v;
            } else {
                if (col < Prows)
                    *(float2*)(C + (size_t)rr * Prows + col) = v;
            }
        }
    }
}

// ---------------- counting sort of edges by segment ------------------------
__global__ void k_zero()
{
    int i = blockIdx.x * blockDim.x + threadIdx.x;
    if (i < RNSEG) { g_cnt[i] = 0; g_cursor[i] = 0; }
}

__global__ void k_hist(const int* __restrict__ ei, const int* __restrict__ et)
{
    int e = blockIdx.x * blockDim.x + threadIdx.x;
    if (e >= EE) return;
    int i64 = g_ei64, t64 = g_et64;
    int dst = load_idx(ei, EE + e, i64);
    int r   = load_idx(et, e, t64);
    atomicAdd(&g_cnt[r * NN + dst], 1);
}

__global__ void k_scan1()
{
    __shared__ int sh[256];
    int t = threadIdx.x;
    int base = blockIdx.x * 1024 + t * 4;
    int v0 = 0, v1 = 0, v2 = 0, v3 = 0;
    if (base + 0 < RNSEG) v0 = g_cnt[base + 0];
    if (base + 1 < RNSEG) v1 = g_cnt[base + 1];
    if (base + 2 < RNSEG) v2 = g_cnt[base + 2];
    if (base + 3 < RNSEG) v3 = g_cnt[base + 3];
    int local = v0 + v1 + v2 + v3;
    sh[t] = local;
    __syncthreads();
    for (int off = 1; off < 256; off <<= 1) {
        int x = 0;
        if (t >= off) x = sh[t - off];
        __syncthreads();
        if (t >= off) sh[t] += x;
        __syncthreads();
    }
    int run = sh[t] - local;
    if (base + 0 < RNSEG) g_start[base + 0] = run;  run += v0;
    if (base + 1 < RNSEG) g_start[base + 1] = run;  run += v1;
    if (base + 2 < RNSEG) g_start[base + 2] = run;  run += v2;
    if (base + 3 < RNSEG) g_start[base + 3] = run;
    if (t == 255) g_bsum[blockIdx.x] = sh[255];
}

__global__ void k_scan2(int nb)
{
    __shared__ int sh[512];
    int t = threadIdx.x;
    int val = (t < nb) ? g_bsum[t] : 0;
    sh[t] = val;
    __syncthreads();
    for (int off = 1; off < 512; off <<= 1) {
        int x = 0;
        if (t >= off) x = sh[t - off];
        __syncthreads();
        if (t >= off) sh[t] += x;
        __syncthreads();
    }
    if (t < nb) g_bsum[t] = sh[t] - val;
}

__global__ void k_scan3()
{
    int i = blockIdx.x * blockDim.x + threadIdx.x;
    if (i < RNSEG) g_start[i] += g_bsum[i >> 10];
}

__global__ void k_scatter(const int* __restrict__ ei, const int* __restrict__ et)
{
    int e = blockIdx.x * blockDim.x + threadIdx.x;
    if (e >= EE) return;
    int i64 = g_ei64, t64 = g_et64;
    int src = load_idx(ei, e, i64);
    int dst = load_idx(ei, EE + e, i64);
    int r   = load_idx(et, e, t64);
    int seg = r * NN + dst;
    int pos = g_start[seg] + atomicAdd(&g_cursor[seg], 1);
    g_ssrc[pos] = src;
}

// ---------------- per-segment softmax-weighted aggregation -----------------
// N-MAJOR mapping: block = node n, warp = relation r. All 8 warps of a block
// share the same sn/hi cache lines (L1 hits) instead of re-fetching them 8x
// across distant r-stripes. Segment ids & z layout unchanged (seg = r*NN+n).
// Single online pass: acc = sum e_j*xj, denom = sum e_j; z = sn + acc/denom.
__global__ __launch_bounds__(256)
void k_agg(const float* __restrict__ natt)
{
    int n    = blockIdx.x;                 // node
    int r    = threadIdx.x >> 5;           // relation = warp id (8 warps)
    int lane = threadIdx.x & 31;
    int seg  = r * NN + n;
    int d0 = lane * 4;

    float4 sn4 = *(const float4*)(g_sn + (size_t)n * HC + d0);
    float4 acc = make_float4(0.f, 0.f, 0.f, 0.f);
    float denom = 0.f;
    int cnt = g_cnt[seg];

    if (cnt > 0) {
        int st = g_start[seg];
        float4 xi = *(const float4*)(g_hi + (size_t)n * HC + d0);
        int h  = lane >> 3;
        int cb = (lane & 7) * 4;
        const float* ab = natt + (r * HH + h) * (2 * CC);
        float4 ai = *(const float4*)(ab + cb);
        float4 aj = *(const float4*)(ab + CC + cb);

        float pi = ai.x * xi.x + ai.y * xi.y + ai.z * xi.z + ai.w * xi.w;
        pi += __shfl_xor_sync(0xffffffffu, pi, 1);
        pi += __shfl_xor_sync(0xffffffffu, pi, 2);
        pi += __shfl_xor_sync(0xffffffffu, pi, 4);

        for (int j = 0; j < cnt; j++) {
            int src = g_ssrc[st + j];
            float4 xj = *(const float4*)(g_hj + (size_t)src * HC + d0);
            float pj = aj.x * xj.x + aj.y * xj.y + aj.z * xj.z + aj.w * xj.w;
            pj += __shfl_xor_sync(0xffffffffu, pj, 1);
            pj += __shfl_xor_sync(0xffffffffu, pj, 2);
            pj += __shfl_xor_sync(0xffffffffu, pj, 4);
            float al = pi + pj;
            al = (al > 0.f) ? al : 0.2f * al;        // leaky relu
            float e = __expf(al);
            denom += e;
            acc.x += e * xj.x; acc.y += e * xj.y;
            acc.z += e * xj.z; acc.w += e * xj.w;
        }
        float inv = 1.f / (denom + 1e-16f);
        acc.x *= inv; acc.y *= inv; acc.z *= inv; acc.w *= inv;
    }
    float zr[4] = { sn4.x + acc.x, sn4.y + acc.y, sn4.z + acc.z, sn4.w + acc.w };
    __half hh[4], ll[4];
#pragma unroll
    for (int t = 0; t < 4; t++) {
        hh[t] = __float2half(zr[t]);
        ll[t] = __float2half(zr[t] - __half2float(hh[t]));
    }
    *(uint2*)(g_zh + (size_t)seg * HC + d0) = *(uint2*)hh;
    *(uint2*)(g_zl + (size_t)seg * HC + d0) = *(uint2*)ll;
}

// ---------------- relation-level attention + output ------------------------
__global__ void k_final(const float* __restrict__ wrel, float* __restrict__ out)
{
    int n    = (blockIdx.x * blockDim.x + threadIdx.x) >> 5;
    int lane = threadIdx.x & 31;
    if (n >= NN) return;

    float q[RR], kk[RR], vv[RR];
#pragma unroll
    for (int r = 0; r < RR; r++) {
        const float* p = g_qkvb + ((size_t)r * NN + n) * QKVP;
        q[r]  = p[lane];
        kk[r] = p[32 + lane];
        vv[r] = p[64 + lane];
    }
    float selfc = g_self[(size_t)n * CC + lane];
    float o = 0.f;

#pragma unroll
    for (int r = 0; r < RR; r++) {
        float t[RR];
#pragma unroll
        for (int s = 0; s < RR; s++) t[s] = q[r] * kk[s];
#pragma unroll
        for (int off = 16; off > 0; off >>= 1)
#pragma unroll
            for (int s = 0; s < RR; s++)
                t[s] += __shfl_xor_sync(0xffffffffu, t[s], off);
        float m = t[0];
#pragma unroll
        for (int s = 1; s < RR; s++) m = fmaxf(m, t[s]);
        float psum = 0.f, dacc = 0.f;
#pragma unroll
        for (int s = 0; s < RR; s++) {
            float e = __expf(t[s] - m);
            psum += e;
            dacc += e * vv[s];
        }
        float delta = dacc / psum;
        float sd = delta;
#pragma unroll
        for (int off = 16; off > 0; off >>= 1)
            sd += __shfl_xor_sync(0xffffffffu, sd, off);
        float mask = (sd != 0.f) ? 1.f : 0.f;
        o += (delta + selfc * mask) * wrel[r];
    }
    out[n * CC + lane] = o;
}

// ---------------- host launcher --------------------------------------------
extern "C" void kernel_launch(void* const* d_in, const int* in_sizes, int n_in,
                              void* d_out, int out_size)
{
    (void)in_sizes; (void)n_in; (void)out_size;
    const float* x    = (const float*)d_in[0];
    const int*   ei   = (const int*)d_in[1];    // int32 OR int64 (sniffed)
    const int*   et   = (const int*)d_in[2];
    const float* Wj   = (const float*)d_in[3];
    const float* Wi   = (const float*)d_in[4];
    const float* natt = (const float*)d_in[5];
    const float* Wq   = (const float*)d_in[6];
    const float* Wk   = (const float*)d_in[7];
    const float* Wv   = (const float*)d_in[8];
    const float* Wself= (const float*)d_in[9];
    const float* Wsn  = (const float*)d_in[10];
    const float* Wrel = (const float*)d_in[11];
    float*       out  = (float*)d_out;

    const int SM_NODE = 2 * ASZ + 2 * 64 * ROWB;   // 104448 -> 2 CTAs/SM
    const int SM_QKV  = 2 * ASZ + 2 * 48 * ROWB;   //  95744 -> 2 CTAs/SM
    cudaFuncSetAttribute(tgemm<64, 0>, cudaFuncAttributeMaxDynamicSharedMemorySize, SM_NODE);
    cudaFuncSetAttribute(tgemm<48, 1>, cudaFuncAttributeMaxDynamicSharedMemorySize, SM_QKV);

    void *xh, *xl, *zh, *zl, *qkv, *wnh, *wnl, *wqh, *wql;
    cudaGetSymbolAddress(&xh,  g_xh);   cudaGetSymbolAddress(&xl,  g_xl);
    cudaGetSymbolAddress(&zh,  g_zh);   cudaGetSymbolAddress(&zl,  g_zl);
    cudaGetSymbolAddress(&qkv, g_qkvb);
    cudaGetSymbolAddress(&wnh, g_wnh);  cudaGetSymbolAddress(&wnl, g_wnl);
    cudaGetSymbolAddress(&wqh, g_wqh);  cudaGetSymbolAddress(&wql, g_wql);

    const int MBLK = (NN + 127) / 128;   // 391

    // (1) dtype sniff, (2) fused conversions
    k_detect<<<1, 1>>>(ei, et);
    k_prep<<<(PREP_TOT + 255) / 256, 256>>>(x, Wj, Wi, Wsn, Wself, Wq, Wk, Wv);

    // (3) fused node projections early (also lands in ncu's sampling window)
    tgemm<64, 0><<<dim3(7, MBLK, 1), 256, SM_NODE>>>(
        (const __half*)xh, (const __half*)xl,
        (const __half*)wnh, (const __half*)wnl,
        nullptr, NN, NODEP, 0, 0, 0);

    // (4-9) counting sort of edges by segment
    k_zero<<<(RNSEG + 255) / 256, 256>>>();
    k_hist<<<(EE + 255) / 256, 256>>>(ei, et);
    k_scan1<<<NB1, 256>>>();
    k_scan2<<<1, 512>>>(NB1);
    k_scan3<<<(RNSEG + 255) / 256, 256>>>();
    k_scatter<<<(EE + 255) / 256, 256>>>(ei, et);

    // (10) per-node (all relations) attention aggregation -> z (fp16 hi/lo)
    k_agg<<<NN, 256>>>(natt);

    // (11) batched qkv projection: q|k|v[r] = z[r] @ [Wq|Wk|Wv][r]
    tgemm<48, 1><<<dim3(2, MBLK, RR), 256, SM_QKV>>>(
        (const __half*)zh, (const __half*)zl,
        (const __half*)wqh, (const __half*)wql,
        (float*)qkv, NN, QKVP,
        (long long)NN * HC, (long long)QKVP * HC, (long long)NN * QKVP);

    // (12) relation attention + output
    k_final<<<(NN + 7) / 8, 256>>>(Wrel, out);
}